// round 15
// baseline (speedup 1.0000x reference)
#include <cuda_runtime.h>
#include <cstdint>

// Problem constants
#define KS   17
#define HP   256
#define WP   256
#define HI   (HP + KS - 1)   // 272
#define WI   (WP + KS - 1)   // 272
#define P    (HP * WP)       // 65536
#define IMG_BC_STRIDE (HI * WI)

// Tiling (round-6 shape, best so far): block = 128 px of ONE row x all 12 bc.
//   threads: (32,4) = 128; thread = 4 px x 3 bc
//   grid   : (2,256) = 512 blocks
// NEW in round 9: free-running warp pipeline. No per-iteration __syncthreads.
// Each stage has a FULL mbarrier (TMA tx-count) and an EMPTY mbarrier
// (count = 128; every thread arrives after consuming). Only thread 0 (the
// TMA producer) ever waits on EMPTY. Consumer warps skew up to NSTAGE-1
// iterations, hiding each other's latencies.
#define TILE_X       128
#define NSTAGE       4
#define CHUNK_BYTES  (TILE_X * 4)        // 512
#define STAGE_FLOATS (KS * TILE_X)       // 2176
#define STAGE_BYTES  (STAGE_FLOATS * 4)  // 8704
#define NTHREADS     128

__device__ __forceinline__ void mbar_init(uint32_t a, uint32_t cnt) {
    asm volatile("mbarrier.init.shared.b64 [%0], %1;" :: "r"(a), "r"(cnt) : "memory");
}
__device__ __forceinline__ void mbar_expect_tx(uint32_t a, uint32_t bytes) {
    asm volatile("mbarrier.arrive.expect_tx.shared.b64 _, [%0], %1;"
                 :: "r"(a), "r"(bytes) : "memory");
}
__device__ __forceinline__ void mbar_arrive(uint32_t a) {
    asm volatile("mbarrier.arrive.release.cta.shared::cta.b64 _, [%0];"
                 :: "r"(a) : "memory");
}
__device__ __forceinline__ void mbar_wait(uint32_t a, uint32_t parity) {
    asm volatile(
        "{\n\t"
        ".reg .pred p;\n\t"
        "WAIT_%=: mbarrier.try_wait.parity.acquire.cta.shared::cta.b64 p, [%0], %1, 0x989680;\n\t"
        "@p bra.uni DONE_%=;\n\t"
        "bra.uni WAIT_%=;\n\t"
        "DONE_%=:\n\t"
        "}"
        :: "r"(a), "r"(parity) : "memory");
}
__device__ __forceinline__ void bulk_g2s(uint32_t dst, const void* src,
                                         uint32_t bytes, uint32_t bar) {
    asm volatile(
        "cp.async.bulk.shared::cta.global.mbarrier::complete_tx::bytes [%0], [%1], %2, [%3];"
        :: "r"(dst), "l"(src), "r"(bytes), "r"(bar) : "memory");
}

__global__ void __launch_bounds__(NTHREADS, 4)
blur_kernel(const float* __restrict__ img,
            const float* __restrict__ kernels,
            const int*   __restrict__ idx_p,
            float*       __restrict__ out)
{
    __shared__ __align__(16) float    skern[NSTAGE * STAGE_FLOATS];
    __shared__ __align__(8)  uint64_t fullbar[NSTAGE];
    __shared__ __align__(8)  uint64_t emptybar[NSTAGE];

    const int tx  = threadIdx.x;          // 0..31 -> 4 px each
    const int ty  = threadIdx.y;          // 0..3  -> 3 bc each
    const int tid = tx + ty * 32;

    const int xblk = blockIdx.x * TILE_X;
    const int y0   = blockIdx.y;
    const int xt   = xblk + tx * 4;
    const int bc0  = ty * 3;
    const int p0   = y0 * WP + xt;

    const long long kidx = (long long)(*idx_p);
    const float* __restrict__ kern_blk =
        kernels + kidx * (long long)(KS * KS) * (long long)P
                + (long long)y0 * WP + xblk;

    const uint32_t sker = (uint32_t)__cvta_generic_to_shared(skern);
    const uint32_t sful = (uint32_t)__cvta_generic_to_shared(fullbar);
    const uint32_t semp = (uint32_t)__cvta_generic_to_shared(emptybar);

    if (tid == 0) {
#pragma unroll
        for (int s = 0; s < NSTAGE; s++) {
            mbar_init(sful + s * 8, 1);
            mbar_init(semp + s * 8, NTHREADS);
        }
    }
    asm volatile("fence.proxy.async.shared::cta;" ::: "memory");
    __syncthreads();

    auto issue_stage = [&](int s, int kh) {
        const uint32_t bar = sful + s * 8;
        mbar_expect_tx(bar, STAGE_BYTES);
        const uint32_t dst0 = sker + (uint32_t)(s * STAGE_BYTES);
#pragma unroll
        for (int kw = 0; kw < KS; kw++) {
            bulk_g2s(dst0 + kw * CHUNK_BYTES,
                     kern_blk + (long long)(kh * KS + kw) * P,
                     CHUNK_BYTES, bar);
        }
    };

    if (tid == 0) {
        issue_stage(0, 0);
        issue_stage(1, 1);
        issue_stage(2, 2);
        issue_stage(3, 3);
    }

    float acc[3][4];
#pragma unroll
    for (int bc = 0; bc < 3; bc++)
#pragma unroll
        for (int r = 0; r < 4; r++) acc[bc][r] = 0.0f;

#pragma unroll 1
    for (int kh = 0; kh < KS; kh++) {
        const int s  = kh & (NSTAGE - 1);
        const int ph = (kh >> 2) & 1;

        // img window: issue the 15 LDG.128 (L2-resident) BEFORE waiting on the
        // stage so L2 latency overlaps the mbarrier wait.
        const float* __restrict__ irow =
            img + (long long)bc0 * IMG_BC_STRIDE + (long long)(y0 + kh) * WI + xt;
        float win[3][20];
#pragma unroll
        for (int bc = 0; bc < 3; bc++) {
#pragma unroll
            for (int v = 0; v < 5; v++) {
                const float4 t = *(const float4*)(irow + bc * IMG_BC_STRIDE + v * 4);
                win[bc][v * 4 + 0] = t.x;
                win[bc][v * 4 + 1] = t.y;
                win[bc][v * 4 + 2] = t.z;
                win[bc][v * 4 + 3] = t.w;
            }
        }

        mbar_wait(sful + s * 8, (uint32_t)ph);

        const float* __restrict__ srow = skern + s * STAGE_FLOATS + tx * 4;
#pragma unroll
        for (int kw = 0; kw < KS; kw++) {
            const float4 w = *(const float4*)(srow + kw * TILE_X);
#pragma unroll
            for (int bc = 0; bc < 3; bc++) {
                acc[bc][0] = fmaf(w.x, win[bc][kw + 0], acc[bc][0]);
                acc[bc][1] = fmaf(w.y, win[bc][kw + 1], acc[bc][1]);
                acc[bc][2] = fmaf(w.z, win[bc][kw + 2], acc[bc][2]);
                acc[bc][3] = fmaf(w.w, win[bc][kw + 3], acc[bc][3]);
            }
        }

        // done with stage s for this round — free it (no block-wide sync!)
        mbar_arrive(semp + s * 8);

        // producer: refill stage s for kh+NSTAGE once ALL threads have freed it
        if (tid == 0 && kh + NSTAGE < KS) {
            mbar_wait(semp + s * 8, (uint32_t)((kh >> 2) & 1));
            issue_stage(s, kh + NSTAGE);
        }
    }

#pragma unroll
    for (int bc = 0; bc < 3; bc++) {
        *(float4*)(out + (long long)(bc0 + bc) * P + p0) =
            make_float4(acc[bc][0], acc[bc][1], acc[bc][2], acc[bc][3]);
    }
}

extern "C" void kernel_launch(void* const* d_in, const int* in_sizes, int n_in,
                              void* d_out, int out_size)
{
    const float* img     = (const float*)d_in[0];  // (4,3,272,272) f32
    const float* kernels = (const float*)d_in[1];  // (16,1,289,65536) f32
    const int*   idx     = (const int*)d_in[2];    // scalar int32
    float*       out     = (float*)d_out;          // (4,3,256,256) f32

    dim3 block(32, 4);                  // 128 threads
    dim3 grid(WP / TILE_X, HP);         // (2,256) = 512 blocks
    blur_kernel<<<grid, block>>>(img, kernels, idx, out);
}

// round 16
// speedup vs baseline: 1.0083x; 1.0083x over previous
#include <cuda_runtime.h>
#include <cstdint>

// Problem constants
#define KS   17
#define HP   256
#define WP   256
#define HI   (HP + KS - 1)   // 272
#define WI   (WP + KS - 1)   // 272
#define P    (HP * WP)       // 65536
#define IMG_BC_STRIDE (HI * WI)

// Tiling (round-6 shape, best so far): block = 128 px of ONE row x all 12 bc.
//   threads: (32,4) = 128; thread = 4 px x 3 bc
//   grid   : (2,256) = 512 blocks
// NEW in round 9: free-running warp pipeline. No per-iteration __syncthreads.
// Each stage has a FULL mbarrier (TMA tx-count) and an EMPTY mbarrier
// (count = 128; every thread arrives after consuming). Only thread 0 (the
// TMA producer) ever waits on EMPTY. Consumer warps skew up to NSTAGE-1
// iterations, hiding each other's latencies.
#define TILE_X       128
#define NSTAGE       4
#define CHUNK_BYTES  (TILE_X * 4)        // 512
#define STAGE_FLOATS (KS * TILE_X)       // 2176
#define STAGE_BYTES  (STAGE_FLOATS * 4)  // 8704
#define NTHREADS     128

__device__ __forceinline__ void mbar_init(uint32_t a, uint32_t cnt) {
    asm volatile("mbarrier.init.shared.b64 [%0], %1;" :: "r"(a), "r"(cnt) : "memory");
}
__device__ __forceinline__ void mbar_expect_tx(uint32_t a, uint32_t bytes) {
    asm volatile("mbarrier.arrive.expect_tx.shared.b64 _, [%0], %1;"
                 :: "r"(a), "r"(bytes) : "memory");
}
__device__ __forceinline__ void mbar_arrive(uint32_t a) {
    asm volatile("mbarrier.arrive.release.cta.shared::cta.b64 _, [%0];"
                 :: "r"(a) : "memory");
}
__device__ __forceinline__ void mbar_wait(uint32_t a, uint32_t parity) {
    asm volatile(
        "{\n\t"
        ".reg .pred p;\n\t"
        "WAIT_%=: mbarrier.try_wait.parity.acquire.cta.shared::cta.b64 p, [%0], %1, 0x989680;\n\t"
        "@p bra.uni DONE_%=;\n\t"
        "bra.uni WAIT_%=;\n\t"
        "DONE_%=:\n\t"
        "}"
        :: "r"(a), "r"(parity) : "memory");
}
__device__ __forceinline__ void bulk_g2s(uint32_t dst, const void* src,
                                         uint32_t bytes, uint32_t bar) {
    asm volatile(
        "cp.async.bulk.shared::cta.global.mbarrier::complete_tx::bytes [%0], [%1], %2, [%3];"
        :: "r"(dst), "l"(src), "r"(bytes), "r"(bar) : "memory");
}

__global__ void __launch_bounds__(NTHREADS, 4)
blur_kernel(const float* __restrict__ img,
            const float* __restrict__ kernels,
            const int*   __restrict__ idx_p,
            float*       __restrict__ out)
{
    __shared__ __align__(16) float    skern[NSTAGE * STAGE_FLOATS];
    __shared__ __align__(8)  uint64_t fullbar[NSTAGE];
    __shared__ __align__(8)  uint64_t emptybar[NSTAGE];

    const int tx  = threadIdx.x;          // 0..31 -> 4 px each
    const int ty  = threadIdx.y;          // 0..3  -> 3 bc each
    const int tid = tx + ty * 32;

    const int xblk = blockIdx.x * TILE_X;
    const int y0   = blockIdx.y;
    const int xt   = xblk + tx * 4;
    const int bc0  = ty * 3;
    const int p0   = y0 * WP + xt;

    const long long kidx = (long long)(*idx_p);
    const float* __restrict__ kern_blk =
        kernels + kidx * (long long)(KS * KS) * (long long)P
                + (long long)y0 * WP + xblk;

    const uint32_t sker = (uint32_t)__cvta_generic_to_shared(skern);
    const uint32_t sful = (uint32_t)__cvta_generic_to_shared(fullbar);
    const uint32_t semp = (uint32_t)__cvta_generic_to_shared(emptybar);

    if (tid == 0) {
#pragma unroll
        for (int s = 0; s < NSTAGE; s++) {
            mbar_init(sful + s * 8, 1);
            mbar_init(semp + s * 8, NTHREADS);
        }
    }
    asm volatile("fence.proxy.async.shared::cta;" ::: "memory");
    __syncthreads();

    auto issue_stage = [&](int s, int kh) {
        const uint32_t bar = sful + s * 8;
        mbar_expect_tx(bar, STAGE_BYTES);
        const uint32_t dst0 = sker + (uint32_t)(s * STAGE_BYTES);
#pragma unroll
        for (int kw = 0; kw < KS; kw++) {
            bulk_g2s(dst0 + kw * CHUNK_BYTES,
                     kern_blk + (long long)(kh * KS + kw) * P,
                     CHUNK_BYTES, bar);
        }
    };

    if (tid == 0) {
        issue_stage(0, 0);
        issue_stage(1, 1);
        issue_stage(2, 2);
        issue_stage(3, 3);
    }

    float acc[3][4];
#pragma unroll
    for (int bc = 0; bc < 3; bc++)
#pragma unroll
        for (int r = 0; r < 4; r++) acc[bc][r] = 0.0f;

#pragma unroll 1
    for (int kh = 0; kh < KS; kh++) {
        const int s  = kh & (NSTAGE - 1);
        const int ph = (kh >> 2) & 1;

        // img window: issue the 15 LDG.128 (L2-resident) BEFORE waiting on the
        // stage so L2 latency overlaps the mbarrier wait.
        const float* __restrict__ irow =
            img + (long long)bc0 * IMG_BC_STRIDE + (long long)(y0 + kh) * WI + xt;
        float win[3][20];
#pragma unroll
        for (int bc = 0; bc < 3; bc++) {
#pragma unroll
            for (int v = 0; v < 5; v++) {
                const float4 t = *(const float4*)(irow + bc * IMG_BC_STRIDE + v * 4);
                win[bc][v * 4 + 0] = t.x;
                win[bc][v * 4 + 1] = t.y;
                win[bc][v * 4 + 2] = t.z;
                win[bc][v * 4 + 3] = t.w;
            }
        }

        mbar_wait(sful + s * 8, (uint32_t)ph);

        const float* __restrict__ srow = skern + s * STAGE_FLOATS + tx * 4;
#pragma unroll
        for (int kw = 0; kw < KS; kw++) {
            const float4 w = *(const float4*)(srow + kw * TILE_X);
#pragma unroll
            for (int bc = 0; bc < 3; bc++) {
                acc[bc][0] = fmaf(w.x, win[bc][kw + 0], acc[bc][0]);
                acc[bc][1] = fmaf(w.y, win[bc][kw + 1], acc[bc][1]);
                acc[bc][2] = fmaf(w.z, win[bc][kw + 2], acc[bc][2]);
                acc[bc][3] = fmaf(w.w, win[bc][kw + 3], acc[bc][3]);
            }
        }

        // done with stage s for this round — free it (no block-wide sync!)
        mbar_arrive(semp + s * 8);

        // producer: refill stage s for kh+NSTAGE once ALL threads have freed it
        if (tid == 0 && kh + NSTAGE < KS) {
            mbar_wait(semp + s * 8, (uint32_t)((kh >> 2) & 1));
            issue_stage(s, kh + NSTAGE);
        }
    }

#pragma unroll
    for (int bc = 0; bc < 3; bc++) {
        *(float4*)(out + (long long)(bc0 + bc) * P + p0) =
            make_float4(acc[bc][0], acc[bc][1], acc[bc][2], acc[bc][3]);
    }
}

extern "C" void kernel_launch(void* const* d_in, const int* in_sizes, int n_in,
                              void* d_out, int out_size)
{
    const float* img     = (const float*)d_in[0];  // (4,3,272,272) f32
    const float* kernels = (const float*)d_in[1];  // (16,1,289,65536) f32
    const int*   idx     = (const int*)d_in[2];    // scalar int32
    float*       out     = (float*)d_out;          // (4,3,256,256) f32

    dim3 block(32, 4);                  // 128 threads
    dim3 grid(WP / TILE_X, HP);         // (2,256) = 512 blocks
    blur_kernel<<<grid, block>>>(img, kernels, idx, out);
}